// round 5
// baseline (speedup 1.0000x reference)
#include <cuda_runtime.h>

#define NPTS 16384
#define MTOT 8192
#define M1   4096
#define CIN  64
#define COUT 128
#define KNNK 16
#define CF   67   // 3 + 64

// ---- output layout (floats) ----
#define OFF_NP1 0
#define OFF_X1  12288
#define OFF_NO1 536576
#define OFF_NP2 536577
#define OFF_X2  548865
#define OFF_NO2 1073153

// ---- device scratch (no allocations allowed) ----
__device__ int   g_idx[MTOT];
__device__ int   g_knn[MTOT * KNNK];
__device__ float g_h[(size_t)MTOT * KNNK * COUT];   // 64 MB
__device__ float g_scale[2 * COUT];
__device__ float g_shift[2 * COUT];

// ============================================================
// 1. FPS — single CTA, 1024 threads, points in SMEM, dists in regs.
//    Distance = fma(dz,dz, fma(dx,dx, dy*dy))
//    (LLVM LHS-first contraction of the unrolled XLA reduce)
//    argmax tie-break: FIRST index (validated)
// ============================================================
__global__ void __launch_bounds__(1024, 1)
fps_kernel(const float* __restrict__ p)
{
    extern __shared__ float sm[];
    float* spx = sm;
    float* spy = sm + NPTS;
    float* spz = sm + 2 * NPTS;
    __shared__ float sv[32];
    __shared__ int   si[32];
    __shared__ float slast[3];

    int tid = threadIdx.x;
    for (int i = tid; i < NPTS; i += 1024) {
        spx[i] = p[3 * i];
        spy[i] = p[3 * i + 1];
        spz[i] = p[3 * i + 2];
    }
    if (tid == 0) {
        slast[0] = p[0]; slast[1] = p[1]; slast[2] = p[2];
        g_idx[0] = 0;
    }
    float dd[16];
    #pragma unroll
    for (int j = 0; j < 16; j++) dd[j] = 1e10f;

    int lane = tid & 31, wid = tid >> 5;
    __syncthreads();

    for (int t = 1; t < MTOT; ++t) {
        float lx = slast[0], ly = slast[1], lz = slast[2];
        float bv = -1.0f;
        int   bi = 0;
        #pragma unroll
        for (int j = 0; j < 16; j++) {
            int i = tid + j * 1024;             // strided ownership: conflict-free LDS
            float dx = __fsub_rn(spx[i], lx);
            float dy = __fsub_rn(spy[i], ly);
            float dz = __fsub_rn(spz[i], lz);
            // LHS-fused chain: fma(dz,dz, fma(dx,dx, dy*dy))
            float d  = __fmaf_rn(dz, dz, __fmaf_rn(dx, dx, __fmul_rn(dy, dy)));
            float nd = fminf(dd[j], d);
            dd[j] = nd;
            if (nd > bv) { bv = nd; bi = i; }   // i ascending in j -> first-index on tie
        }
        // warp argmax (value desc, index asc on tie)
        #pragma unroll
        for (int off = 16; off > 0; off >>= 1) {
            float ov = __shfl_down_sync(0xffffffffu, bv, off);
            int   oi = __shfl_down_sync(0xffffffffu, bi, off);
            if (ov > bv || (ov == bv && oi < bi)) { bv = ov; bi = oi; }
        }
        if (lane == 0) { sv[wid] = bv; si[wid] = bi; }
        __syncthreads();
        if (tid < 32) {
            bv = sv[tid]; bi = si[tid];
            #pragma unroll
            for (int off = 16; off > 0; off >>= 1) {
                float ov = __shfl_down_sync(0xffffffffu, bv, off);
                int   oi = __shfl_down_sync(0xffffffffu, bi, off);
                if (ov > bv || (ov == bv && oi < bi)) { bv = ov; bi = oi; }
            }
            if (tid == 0) {
                g_idx[t] = bi;
                slast[0] = spx[bi]; slast[1] = spy[bi]; slast[2] = spz[bi];
            }
        }
        __syncthreads();
    }
}

// ============================================================
// 2. Gather sampled coordinates + n_o scalars into output
// ============================================================
__global__ void gather_kernel(const float* __restrict__ p, float* __restrict__ out)
{
    int e = blockIdx.x * blockDim.x + threadIdx.x;
    if (e < MTOT * 3) {
        int q = e / 3, d = e - 3 * q;
        float v = p[g_idx[q] * 3 + d];
        int pos = (q < M1) ? (OFF_NP1 + e) : (OFF_NP2 + (e - M1 * 3));
        out[pos] = v;
    } else if (e == MTOT * 3) {
        out[OFF_NO1] = 4096.0f;
    } else if (e == MTOT * 3 + 1) {
        out[OFF_NO2] = 4096.0f;
    }
}

// ============================================================
// 3. KNN — thread-per-query, SMEM point tiles (broadcast reads),
//    per-thread sorted top-16
// ============================================================
__global__ void __launch_bounds__(128, 8)
knn_kernel(const float* __restrict__ p)
{
    __shared__ float4 tile[2048];   // 32 KB
    int tid = threadIdx.x;
    int qid = blockIdx.x * 128 + tid;
    int qi = g_idx[qid];
    float qx = p[3 * qi], qy = p[3 * qi + 1], qz = p[3 * qi + 2];
    float qq = qx * qx + qy * qy + qz * qz;

    float bd[16]; int bn[16];
    #pragma unroll
    for (int i = 0; i < 16; i++) { bd[i] = 3.4e38f; bn[i] = 0; }

    for (int tb = 0; tb < 8; tb++) {
        for (int i = tid; i < 2048; i += 128) {
            int g = tb * 2048 + i;
            float x = p[3 * g], y = p[3 * g + 1], z = p[3 * g + 2];
            tile[i] = make_float4(x, y, z, x * x + y * y + z * z);
        }
        __syncthreads();
        for (int j = 0; j < 2048; j++) {
            float4 t = tile[j];
            float dot = fmaf(qx, t.x, fmaf(qy, t.y, qz * t.z));
            float d = fmaf(-2.0f, dot, qq) + t.w;
            if (d < bd[15]) {
                int g = tb * 2048 + j;
                int k = 15;
                while (k > 0 && bd[k - 1] > d) {
                    bd[k] = bd[k - 1]; bn[k] = bn[k - 1]; --k;
                }
                bd[k] = d; bn[k] = g;
            }
        }
        __syncthreads();
    }
    #pragma unroll
    for (int i = 0; i < 16; i++) g_knn[qid * 16 + i] = bn[i];
}

// ============================================================
// 4. Grouped feature build + linear (67 -> 128), h to global
// ============================================================
__global__ void __launch_bounds__(128, 8)
mlp_kernel(const float* __restrict__ p, const float* __restrict__ x,
           const float* __restrict__ W)
{
    __shared__ float f[16 * 68];
    __shared__ int   sn[16];
    __shared__ float qc[3];
    int tid = threadIdx.x, q = blockIdx.x;
    if (tid < 16) sn[tid] = g_knn[q * 16 + tid];
    if (tid < 3)  qc[tid] = p[g_idx[q] * 3 + tid];
    __syncthreads();
    for (int e = tid; e < 16 * CF; e += 128) {
        int s = e / CF, k = e - CF * s;
        int n = sn[s];
        float v = (k < 3) ? (p[n * 3 + k] - qc[k]) : x[n * 64 + (k - 3)];
        f[s * 68 + k] = v;
    }
    __syncthreads();
    float acc[16];
    #pragma unroll
    for (int s = 0; s < 16; s++) acc[s] = 0.f;
    int c = tid;
    for (int k = 0; k < CF; k++) {
        float wv = W[k * 128 + c];
        #pragma unroll
        for (int s = 0; s < 16; s++)
            acc[s] = fmaf(f[s * 68 + k], wv, acc[s]);
    }
    #pragma unroll
    for (int s = 0; s < 16; s++)
        g_h[((size_t)q * 16 + s) * 128 + c] = acc[s];
}

// ============================================================
// 5. Per-half, per-channel BN stats (deterministic tree reduce)
// ============================================================
__global__ void stats_kernel(const float* __restrict__ gamma,
                             const float* __restrict__ beta)
{
    __shared__ float r1[256], r2[256];
    int tid = threadIdx.x;
    int half = blockIdx.x >> 7, c = blockIdx.x & 127;
    const float* base = g_h + (size_t)half * 65536 * 128 + c;
    float s1 = 0.f, s2 = 0.f;
    for (int u = tid; u < 65536; u += 256) {
        float v = base[(size_t)u * 128];
        s1 += v;
        s2 = fmaf(v, v, s2);
    }
    r1[tid] = s1; r2[tid] = s2;
    __syncthreads();
    for (int o = 128; o > 0; o >>= 1) {
        if (tid < o) { r1[tid] += r1[tid + o]; r2[tid] += r2[tid + o]; }
        __syncthreads();
    }
    if (tid == 0) {
        float mean = r1[0] * (1.f / 65536.f);
        float var  = r2[0] * (1.f / 65536.f) - mean * mean;
        float sc = rsqrtf(var + 1e-5f) * gamma[c];
        g_scale[blockIdx.x] = sc;
        g_shift[blockIdx.x] = beta[c] - mean * sc;
    }
}

// ============================================================
// 6. BN apply + ReLU + max-pool over nsample, write x1/x2
// ============================================================
__global__ void __launch_bounds__(128, 8)
pool_kernel(float* __restrict__ out)
{
    int q = blockIdx.x, c = threadIdx.x;
    int half = (q >= M1);
    float sc = g_scale[half * 128 + c];
    float sh = g_shift[half * 128 + c];
    float m = 0.f;   // relu floor; max over 16 relu outputs >= 0
    const float* hb = g_h + ((size_t)q * 16) * 128 + c;
    #pragma unroll
    for (int s = 0; s < 16; s++) {
        float v = fmaf(hb[s * 128], sc, sh);
        v = fmaxf(v, 0.f);
        m = fmaxf(m, v);
    }
    int pos = (q < M1) ? (OFF_X1 + q * 128 + c)
                       : (OFF_X2 + (q - M1) * 128 + c);
    out[pos] = m;
}

// ============================================================
extern "C" void kernel_launch(void* const* d_in, const int* in_sizes, int n_in,
                              void* d_out, int out_size)
{
    const float* p     = (const float*)d_in[0];
    const float* x     = (const float*)d_in[1];
    // d_in[2] = o (int32, unused: single batch)
    const float* W     = (const float*)d_in[3];
    const float* gamma = (const float*)d_in[4];
    const float* beta  = (const float*)d_in[5];
    float* out = (float*)d_out;

    cudaFuncSetAttribute(fps_kernel,
                         cudaFuncAttributeMaxDynamicSharedMemorySize,
                         NPTS * 3 * sizeof(float));

    fps_kernel<<<1, 1024, NPTS * 3 * sizeof(float)>>>(p);
    gather_kernel<<<(MTOT * 3 + 2 + 255) / 256, 256>>>(p, out);
    knn_kernel<<<64, 128>>>(p);
    mlp_kernel<<<MTOT, 128>>>(p, x, W);
    stats_kernel<<<256, 256>>>(gamma, beta);
    pool_kernel<<<MTOT, 128>>>(out);
}

// round 6
// speedup vs baseline: 1.5177x; 1.5177x over previous
#include <cuda_runtime.h>

#define NPTS 16384
#define MTOT 8192
#define M1   4096
#define CIN  64
#define COUT 128
#define KNNK 16
#define CF   67   // 3 + 64

// ---- output layout (floats) ----
#define OFF_NP1 0
#define OFF_X1  12288
#define OFF_NO1 536576
#define OFF_NP2 536577
#define OFF_X2  548865
#define OFF_NO2 1073153

// ---- device scratch (no allocations allowed) ----
__device__ int   g_idx[MTOT];
__device__ int   g_knn[MTOT * KNNK];
__device__ float g_h[(size_t)MTOT * KNNK * COUT];   // 64 MB
__device__ float g_scale[2 * COUT];
__device__ float g_shift[2 * COUT];
// sorted point arrays (Morton order)
__device__ float g_sx[NPTS];
__device__ float g_sy[NPTS];
__device__ float g_sz[NPTS];
__device__ int   g_soi[NPTS];

// ============================================================
// 0. Morton sort — single CTA bitonic sort of (code<<14 | idx)
// ============================================================
__device__ __forceinline__ unsigned expand10(unsigned v)
{
    v &= 1023u;
    v = (v | (v << 16)) & 0x030000FFu;
    v = (v | (v << 8))  & 0x0300F00Fu;
    v = (v | (v << 4))  & 0x030C30C3u;
    v = (v | (v << 2))  & 0x09249249u;
    return v;
}

__global__ void __launch_bounds__(1024, 1)
sort_kernel(const float* __restrict__ p)
{
    extern __shared__ unsigned long long key[];   // 16384 * 8B = 128KB
    __shared__ float rmin[3][32], rmax[3][32];
    __shared__ float bb[6];

    int tid = threadIdx.x, lane = tid & 31, wid = tid >> 5;

    float mn[3] = {1e30f, 1e30f, 1e30f};
    float mx[3] = {-1e30f, -1e30f, -1e30f};
    for (int i = tid; i < NPTS; i += 1024) {
        float c[3] = {p[3 * i], p[3 * i + 1], p[3 * i + 2]};
        #pragma unroll
        for (int d = 0; d < 3; d++) {
            mn[d] = fminf(mn[d], c[d]);
            mx[d] = fmaxf(mx[d], c[d]);
        }
    }
    #pragma unroll
    for (int off = 16; off > 0; off >>= 1) {
        #pragma unroll
        for (int d = 0; d < 3; d++) {
            mn[d] = fminf(mn[d], __shfl_xor_sync(0xffffffffu, mn[d], off));
            mx[d] = fmaxf(mx[d], __shfl_xor_sync(0xffffffffu, mx[d], off));
        }
    }
    if (lane == 0) {
        #pragma unroll
        for (int d = 0; d < 3; d++) { rmin[d][wid] = mn[d]; rmax[d][wid] = mx[d]; }
    }
    __syncthreads();
    if (tid < 32) {
        #pragma unroll
        for (int d = 0; d < 3; d++) { mn[d] = rmin[d][tid]; mx[d] = rmax[d][tid]; }
        #pragma unroll
        for (int off = 16; off > 0; off >>= 1) {
            #pragma unroll
            for (int d = 0; d < 3; d++) {
                mn[d] = fminf(mn[d], __shfl_xor_sync(0xffffffffu, mn[d], off));
                mx[d] = fmaxf(mx[d], __shfl_xor_sync(0xffffffffu, mx[d], off));
            }
        }
        if (tid == 0) {
            #pragma unroll
            for (int d = 0; d < 3; d++) { bb[d] = mn[d]; bb[3 + d] = mx[d]; }
        }
    }
    __syncthreads();

    float ox = bb[0], oy = bb[1], oz = bb[2];
    float scx = 1023.0f / fmaxf(bb[3] - bb[0], 1e-20f);
    float scy = 1023.0f / fmaxf(bb[4] - bb[1], 1e-20f);
    float scz = 1023.0f / fmaxf(bb[5] - bb[2], 1e-20f);

    for (int i = tid; i < NPTS; i += 1024) {
        unsigned xi = (unsigned)fminf(fmaxf((p[3 * i]     - ox) * scx, 0.f), 1023.f);
        unsigned yi = (unsigned)fminf(fmaxf((p[3 * i + 1] - oy) * scy, 0.f), 1023.f);
        unsigned zi = (unsigned)fminf(fmaxf((p[3 * i + 2] - oz) * scz, 0.f), 1023.f);
        unsigned code = (expand10(xi) << 2) | (expand10(yi) << 1) | expand10(zi);
        key[i] = ((unsigned long long)code << 14) | (unsigned)i;
    }
    __syncthreads();

    // bitonic sort
    for (int k = 2; k <= NPTS; k <<= 1) {
        for (int j = k >> 1; j > 0; j >>= 1) {
            for (int t = tid; t < NPTS; t += 1024) {
                int ixj = t ^ j;
                if (ixj > t) {
                    bool up = ((t & k) == 0);
                    unsigned long long a = key[t], b = key[ixj];
                    if ((a > b) == up) { key[t] = b; key[ixj] = a; }
                }
            }
            __syncthreads();
        }
    }

    for (int i = tid; i < NPTS; i += 1024) {
        int oi = (int)(key[i] & 16383ull);
        g_sx[i] = p[3 * oi];
        g_sy[i] = p[3 * oi + 1];
        g_sz[i] = p[3 * oi + 2];
        g_soi[i] = oi;
    }
}

// ============================================================
// 1. FPS — single CTA, Morton-chunked with exact bbox skipping.
//    Distance = fma(dz,dz, fma(dx,dx, dy*dy))  [validated R5]
//    argmax: max value, tie -> min (orig_idx<<14|pos) = first orig index
// ============================================================
__global__ void __launch_bounds__(1024, 1)
fps_kernel(const float* __restrict__ p)
{
    extern __shared__ float sm[];
    float* spx = sm;
    float* spy = sm + NPTS;
    float* spz = sm + 2 * NPTS;
    __shared__ float    sv[32];
    __shared__ unsigned sp[32];
    __shared__ float slast[3];

    int tid = threadIdx.x, lane = tid & 31, wid = tid >> 5;
    int base = tid * 16;

    for (int i = tid; i < NPTS; i += 1024) {
        spx[i] = g_sx[i];
        spy[i] = g_sy[i];
        spz[i] = g_sz[i];
    }
    unsigned opack[16];
    #pragma unroll
    for (int j = 0; j < 16; j++)
        opack[j] = ((unsigned)g_soi[base + j] << 14) | (unsigned)(base + j);

    if (tid == 0) {
        slast[0] = p[0]; slast[1] = p[1]; slast[2] = p[2];
        g_idx[0] = 0;
    }
    __syncthreads();

    // chunk bbox (own 16 contiguous sorted points)
    float bxmin = 1e30f, bymin = 1e30f, bzmin = 1e30f;
    float bxmax = -1e30f, bymax = -1e30f, bzmax = -1e30f;
    #pragma unroll
    for (int j = 0; j < 16; j++) {
        float x = spx[base + j], y = spy[base + j], z = spz[base + j];
        bxmin = fminf(bxmin, x); bxmax = fmaxf(bxmax, x);
        bymin = fminf(bymin, y); bymax = fmaxf(bymax, y);
        bzmin = fminf(bzmin, z); bzmax = fmaxf(bzmax, z);
    }

    float dd[16];
    #pragma unroll
    for (int j = 0; j < 16; j++) dd[j] = 1e10f;
    float    cv = 1e10f;     // cached chunk max  (forces compute on t=1)
    unsigned cp = opack[0];

    for (int t = 1; t < MTOT; ++t) {
        float lx = slast[0], ly = slast[1], lz = slast[2];

        // bbox lower bound on squared distance (safety margin below)
        float ax = fmaxf(fmaxf(bxmin - lx, lx - bxmax), 0.f);
        float ay = fmaxf(fmaxf(bymin - ly, ly - bymax), 0.f);
        float az = fmaxf(fmaxf(bzmin - lz, lz - bzmax), 0.f);
        float lb = ax * ax + ay * ay + az * az;

        if (!(lb * 0.9999f >= cv)) {
            // recompute chunk: exact update + fresh max
            float    ncv = -1.0f;
            unsigned ncp = 0;
            #pragma unroll
            for (int j = 0; j < 16; j++) {
                int i = base + j;
                float dx = __fsub_rn(spx[i], lx);
                float dy = __fsub_rn(spy[i], ly);
                float dz = __fsub_rn(spz[i], lz);
                float d  = __fmaf_rn(dz, dz, __fmaf_rn(dx, dx, __fmul_rn(dy, dy)));
                float nd = fminf(dd[j], d);
                dd[j] = nd;
                unsigned pk = opack[j];
                if (nd > ncv || (nd == ncv && pk < ncp)) { ncv = nd; ncp = pk; }
            }
            cv = ncv; cp = ncp;
        }

        float    bv = cv;
        unsigned bp = cp;
        #pragma unroll
        for (int off = 16; off > 0; off >>= 1) {
            float    ov = __shfl_down_sync(0xffffffffu, bv, off);
            unsigned op = __shfl_down_sync(0xffffffffu, bp, off);
            if (ov > bv || (ov == bv && op < bp)) { bv = ov; bp = op; }
        }
        if (lane == 0) { sv[wid] = bv; sp[wid] = bp; }
        __syncthreads();
        if (tid < 32) {
            bv = sv[tid]; bp = sp[tid];
            #pragma unroll
            for (int off = 16; off > 0; off >>= 1) {
                float    ov = __shfl_down_sync(0xffffffffu, bv, off);
                unsigned op = __shfl_down_sync(0xffffffffu, bp, off);
                if (ov > bv || (ov == bv && op < bp)) { bv = ov; bp = op; }
            }
            if (tid == 0) {
                g_idx[t] = (int)(bp >> 14);
                int pos = (int)(bp & 16383u);
                slast[0] = spx[pos]; slast[1] = spy[pos]; slast[2] = spz[pos];
            }
        }
        __syncthreads();
    }
}

// ============================================================
// 2. Gather sampled coordinates + n_o scalars into output
// ============================================================
__global__ void gather_kernel(const float* __restrict__ p, float* __restrict__ out)
{
    int e = blockIdx.x * blockDim.x + threadIdx.x;
    if (e < MTOT * 3) {
        int q = e / 3, d = e - 3 * q;
        float v = p[g_idx[q] * 3 + d];
        int pos = (q < M1) ? (OFF_NP1 + e) : (OFF_NP2 + (e - M1 * 3));
        out[pos] = v;
    } else if (e == MTOT * 3) {
        out[OFF_NO1] = 4096.0f;
    } else if (e == MTOT * 3 + 1) {
        out[OFF_NO2] = 4096.0f;
    }
}

// ============================================================
// 3. KNN — thread-per-query, SMEM point tiles (broadcast reads),
//    per-thread sorted top-16
// ============================================================
__global__ void __launch_bounds__(128, 8)
knn_kernel(const float* __restrict__ p)
{
    __shared__ float4 tile[2048];   // 32 KB
    int tid = threadIdx.x;
    int qid = blockIdx.x * 128 + tid;
    int qi = g_idx[qid];
    float qx = p[3 * qi], qy = p[3 * qi + 1], qz = p[3 * qi + 2];
    float qq = qx * qx + qy * qy + qz * qz;

    float bd[16]; int bn[16];
    #pragma unroll
    for (int i = 0; i < 16; i++) { bd[i] = 3.4e38f; bn[i] = 0; }

    for (int tb = 0; tb < 8; tb++) {
        for (int i = tid; i < 2048; i += 128) {
            int g = tb * 2048 + i;
            float x = p[3 * g], y = p[3 * g + 1], z = p[3 * g + 2];
            tile[i] = make_float4(x, y, z, x * x + y * y + z * z);
        }
        __syncthreads();
        for (int j = 0; j < 2048; j++) {
            float4 t = tile[j];
            float dot = fmaf(qx, t.x, fmaf(qy, t.y, qz * t.z));
            float d = fmaf(-2.0f, dot, qq) + t.w;
            if (d < bd[15]) {
                int g = tb * 2048 + j;
                int k = 15;
                while (k > 0 && bd[k - 1] > d) {
                    bd[k] = bd[k - 1]; bn[k] = bn[k - 1]; --k;
                }
                bd[k] = d; bn[k] = g;
            }
        }
        __syncthreads();
    }
    #pragma unroll
    for (int i = 0; i < 16; i++) g_knn[qid * 16 + i] = bn[i];
}

// ============================================================
// 4. Grouped feature build + linear (67 -> 128), h to global
// ============================================================
__global__ void __launch_bounds__(128, 8)
mlp_kernel(const float* __restrict__ p, const float* __restrict__ x,
           const float* __restrict__ W)
{
    __shared__ float f[16 * 68];
    __shared__ int   sn[16];
    __shared__ float qc[3];
    int tid = threadIdx.x, q = blockIdx.x;
    if (tid < 16) sn[tid] = g_knn[q * 16 + tid];
    if (tid < 3)  qc[tid] = p[g_idx[q] * 3 + tid];
    __syncthreads();
    for (int e = tid; e < 16 * CF; e += 128) {
        int s = e / CF, k = e - CF * s;
        int n = sn[s];
        float v = (k < 3) ? (p[n * 3 + k] - qc[k]) : x[n * 64 + (k - 3)];
        f[s * 68 + k] = v;
    }
    __syncthreads();
    float acc[16];
    #pragma unroll
    for (int s = 0; s < 16; s++) acc[s] = 0.f;
    int c = tid;
    for (int k = 0; k < CF; k++) {
        float wv = W[k * 128 + c];
        #pragma unroll
        for (int s = 0; s < 16; s++)
            acc[s] = fmaf(f[s * 68 + k], wv, acc[s]);
    }
    #pragma unroll
    for (int s = 0; s < 16; s++)
        g_h[((size_t)q * 16 + s) * 128 + c] = acc[s];
}

// ============================================================
// 5. Per-half, per-channel BN stats (deterministic tree reduce)
// ============================================================
__global__ void stats_kernel(const float* __restrict__ gamma,
                             const float* __restrict__ beta)
{
    __shared__ float r1[256], r2[256];
    int tid = threadIdx.x;
    int half = blockIdx.x >> 7, c = blockIdx.x & 127;
    const float* base = g_h + (size_t)half * 65536 * 128 + c;
    float s1 = 0.f, s2 = 0.f;
    for (int u = tid; u < 65536; u += 256) {
        float v = base[(size_t)u * 128];
        s1 += v;
        s2 = fmaf(v, v, s2);
    }
    r1[tid] = s1; r2[tid] = s2;
    __syncthreads();
    for (int o = 128; o > 0; o >>= 1) {
        if (tid < o) { r1[tid] += r1[tid + o]; r2[tid] += r2[tid + o]; }
        __syncthreads();
    }
    if (tid == 0) {
        float mean = r1[0] * (1.f / 65536.f);
        float var  = r2[0] * (1.f / 65536.f) - mean * mean;
        float sc = rsqrtf(var + 1e-5f) * gamma[c];
        g_scale[blockIdx.x] = sc;
        g_shift[blockIdx.x] = beta[c] - mean * sc;
    }
}

// ============================================================
// 6. BN apply + ReLU + max-pool over nsample, write x1/x2
// ============================================================
__global__ void __launch_bounds__(128, 8)
pool_kernel(float* __restrict__ out)
{
    int q = blockIdx.x, c = threadIdx.x;
    int half = (q >= M1);
    float sc = g_scale[half * 128 + c];
    float sh = g_shift[half * 128 + c];
    float m = 0.f;   // relu floor; max over 16 relu outputs >= 0
    const float* hb = g_h + ((size_t)q * 16) * 128 + c;
    #pragma unroll
    for (int s = 0; s < 16; s++) {
        float v = fmaf(hb[s * 128], sc, sh);
        v = fmaxf(v, 0.f);
        m = fmaxf(m, v);
    }
    int pos = (q < M1) ? (OFF_X1 + q * 128 + c)
                       : (OFF_X2 + (q - M1) * 128 + c);
    out[pos] = m;
}

// ============================================================
extern "C" void kernel_launch(void* const* d_in, const int* in_sizes, int n_in,
                              void* d_out, int out_size)
{
    const float* p     = (const float*)d_in[0];
    const float* x     = (const float*)d_in[1];
    // d_in[2] = o (int32, unused: single batch)
    const float* W     = (const float*)d_in[3];
    const float* gamma = (const float*)d_in[4];
    const float* beta  = (const float*)d_in[5];
    float* out = (float*)d_out;

    cudaFuncSetAttribute(sort_kernel,
                         cudaFuncAttributeMaxDynamicSharedMemorySize,
                         NPTS * sizeof(unsigned long long));
    cudaFuncSetAttribute(fps_kernel,
                         cudaFuncAttributeMaxDynamicSharedMemorySize,
                         NPTS * 3 * sizeof(float));

    sort_kernel<<<1, 1024, NPTS * sizeof(unsigned long long)>>>(p);
    fps_kernel<<<1, 1024, NPTS * 3 * sizeof(float)>>>(p);
    gather_kernel<<<(MTOT * 3 + 2 + 255) / 256, 256>>>(p, out);
    knn_kernel<<<64, 128>>>(p);
    mlp_kernel<<<MTOT, 128>>>(p, x, W);
    stats_kernel<<<256, 256>>>(gamma, beta);
    pool_kernel<<<MTOT, 128>>>(out);
}

// round 7
// speedup vs baseline: 1.8738x; 1.2346x over previous
#include <cuda_runtime.h>

#define NPTS 16384
#define MTOT 8192
#define M1   4096
#define CIN  64
#define COUT 128
#define KNNK 16
#define CF   67   // 3 + 64

// ---- output layout (floats) ----
#define OFF_NP1 0
#define OFF_X1  12288
#define OFF_NO1 536576
#define OFF_NP2 536577
#define OFF_X2  548865
#define OFF_NO2 1073153

// ---- device scratch (no allocations allowed) ----
__device__ int   g_idx[MTOT];
__device__ int   g_knn[MTOT * KNNK];
__device__ float g_h[(size_t)MTOT * KNNK * COUT];   // 64 MB
__device__ float g_scale[2 * COUT];
__device__ float g_shift[2 * COUT];
// sorted point arrays (Morton order)
__device__ float g_sx[NPTS];
__device__ float g_sy[NPTS];
__device__ float g_sz[NPTS];
__device__ unsigned g_sopack[NPTS];   // (orig_idx << 14) | sorted_pos
// BN partial sums
__device__ float g_part1[128 * 128];
__device__ float g_part2[128 * 128];

// ============================================================
// 0. Morton sort — single CTA bitonic sort of (code<<14 | idx)
// ============================================================
__device__ __forceinline__ unsigned expand10(unsigned v)
{
    v &= 1023u;
    v = (v | (v << 16)) & 0x030000FFu;
    v = (v | (v << 8))  & 0x0300F00Fu;
    v = (v | (v << 4))  & 0x030C30C3u;
    v = (v | (v << 2))  & 0x09249249u;
    return v;
}

__global__ void __launch_bounds__(1024, 1)
sort_kernel(const float* __restrict__ p)
{
    extern __shared__ unsigned long long key[];   // 16384 * 8B = 128KB
    __shared__ float rmin[3][32], rmax[3][32];
    __shared__ float bb[6];

    int tid = threadIdx.x, lane = tid & 31, wid = tid >> 5;

    float mn[3] = {1e30f, 1e30f, 1e30f};
    float mx[3] = {-1e30f, -1e30f, -1e30f};
    for (int i = tid; i < NPTS; i += 1024) {
        float c[3] = {p[3 * i], p[3 * i + 1], p[3 * i + 2]};
        #pragma unroll
        for (int d = 0; d < 3; d++) {
            mn[d] = fminf(mn[d], c[d]);
            mx[d] = fmaxf(mx[d], c[d]);
        }
    }
    #pragma unroll
    for (int off = 16; off > 0; off >>= 1) {
        #pragma unroll
        for (int d = 0; d < 3; d++) {
            mn[d] = fminf(mn[d], __shfl_xor_sync(0xffffffffu, mn[d], off));
            mx[d] = fmaxf(mx[d], __shfl_xor_sync(0xffffffffu, mx[d], off));
        }
    }
    if (lane == 0) {
        #pragma unroll
        for (int d = 0; d < 3; d++) { rmin[d][wid] = mn[d]; rmax[d][wid] = mx[d]; }
    }
    __syncthreads();
    if (tid < 32) {
        #pragma unroll
        for (int d = 0; d < 3; d++) { mn[d] = rmin[d][tid]; mx[d] = rmax[d][tid]; }
        #pragma unroll
        for (int off = 16; off > 0; off >>= 1) {
            #pragma unroll
            for (int d = 0; d < 3; d++) {
                mn[d] = fminf(mn[d], __shfl_xor_sync(0xffffffffu, mn[d], off));
                mx[d] = fmaxf(mx[d], __shfl_xor_sync(0xffffffffu, mx[d], off));
            }
        }
        if (tid == 0) {
            #pragma unroll
            for (int d = 0; d < 3; d++) { bb[d] = mn[d]; bb[3 + d] = mx[d]; }
        }
    }
    __syncthreads();

    float ox = bb[0], oy = bb[1], oz = bb[2];
    float scx = 1023.0f / fmaxf(bb[3] - bb[0], 1e-20f);
    float scy = 1023.0f / fmaxf(bb[4] - bb[1], 1e-20f);
    float scz = 1023.0f / fmaxf(bb[5] - bb[2], 1e-20f);

    for (int i = tid; i < NPTS; i += 1024) {
        unsigned xi = (unsigned)fminf(fmaxf((p[3 * i]     - ox) * scx, 0.f), 1023.f);
        unsigned yi = (unsigned)fminf(fmaxf((p[3 * i + 1] - oy) * scy, 0.f), 1023.f);
        unsigned zi = (unsigned)fminf(fmaxf((p[3 * i + 2] - oz) * scz, 0.f), 1023.f);
        unsigned code = (expand10(xi) << 2) | (expand10(yi) << 1) | expand10(zi);
        key[i] = ((unsigned long long)code << 14) | (unsigned)i;
    }
    __syncthreads();

    // bitonic sort
    for (int k = 2; k <= NPTS; k <<= 1) {
        for (int j = k >> 1; j > 0; j >>= 1) {
            for (int t = tid; t < NPTS; t += 1024) {
                int ixj = t ^ j;
                if (ixj > t) {
                    bool up = ((t & k) == 0);
                    unsigned long long a = key[t], b = key[ixj];
                    if ((a > b) == up) { key[t] = b; key[ixj] = a; }
                }
            }
            __syncthreads();
        }
    }

    for (int i = tid; i < NPTS; i += 1024) {
        int oi = (int)(key[i] & 16383ull);
        g_sx[i] = p[3 * oi];
        g_sy[i] = p[3 * oi + 1];
        g_sz[i] = p[3 * oi + 2];
        g_sopack[i] = ((unsigned)oi << 14) | (unsigned)i;
    }
}

// ============================================================
// 1. FPS — single CTA, 512 threads, 32 Morton-contiguous points
//    per thread (2 bbox chunks of 16), transposed SMEM layout
//    (conflict-free), one barrier/iter, redux-based argmax.
//    Distance = fma(dz,dz, fma(dx,dx, dy*dy))  [validated R5]
//    Tie-break: min (orig_idx<<14|pos)  == first original index.
// ============================================================
__global__ void __launch_bounds__(512, 1)
fps_kernel(const float* __restrict__ p)
{
    extern __shared__ float sm[];
    float* spx = sm;                 // [32 slots][512 chunks]
    float* spy = sm + NPTS;
    float* spz = sm + 2 * NPTS;
    __shared__ unsigned svb[2][16], spk[2][16];

    int tid = threadIdx.x, lane = tid & 31, wid = tid >> 5;

    for (int i = tid; i < NPTS; i += 512) {
        int a = ((i & 31) << 9) | (i >> 5);
        spx[a] = g_sx[i];
        spy[a] = g_sy[i];
        spz[a] = g_sz[i];
    }
    unsigned opack[32];
    #pragma unroll
    for (int s = 0; s < 32; s++)
        opack[s] = g_sopack[(tid << 5) + s];

    if (tid == 0) g_idx[0] = 0;
    __syncthreads();

    // per-chunk bboxes: A = slots 0..15, B = slots 16..31
    float Axn = 1e30f, Ayn = 1e30f, Azn = 1e30f;
    float Axm = -1e30f, Aym = -1e30f, Azm = -1e30f;
    float Bxn = 1e30f, Byn = 1e30f, Bzn = 1e30f;
    float Bxm = -1e30f, Bym = -1e30f, Bzm = -1e30f;
    #pragma unroll
    for (int s = 0; s < 16; s++) {
        float x = spx[(s << 9) + tid], y = spy[(s << 9) + tid], z = spz[(s << 9) + tid];
        Axn = fminf(Axn, x); Axm = fmaxf(Axm, x);
        Ayn = fminf(Ayn, y); Aym = fmaxf(Aym, y);
        Azn = fminf(Azn, z); Azm = fmaxf(Azm, z);
    }
    #pragma unroll
    for (int s = 16; s < 32; s++) {
        float x = spx[(s << 9) + tid], y = spy[(s << 9) + tid], z = spz[(s << 9) + tid];
        Bxn = fminf(Bxn, x); Bxm = fmaxf(Bxm, x);
        Byn = fminf(Byn, y); Bym = fmaxf(Bym, y);
        Bzn = fminf(Bzn, z); Bzm = fmaxf(Bzm, z);
    }

    float dd[32];
    #pragma unroll
    for (int s = 0; s < 32; s++) dd[s] = 1e10f;
    float    cvA = 1e10f, cvB = 1e10f;
    unsigned cpA = 0, cpB = 0;

    float lx = p[0], ly = p[1], lz = p[2];

    for (int t = 1; t < MTOT; ++t) {
        int buf = t & 1;
        // ---- chunk A ----
        {
            float ax = fmaxf(fmaxf(Axn - lx, lx - Axm), 0.f);
            float ay = fmaxf(fmaxf(Ayn - ly, ly - Aym), 0.f);
            float az = fmaxf(fmaxf(Azn - lz, lz - Azm), 0.f);
            float lb = ax * ax + ay * ay + az * az;
            if (!(lb * 0.9999f >= cvA)) {
                float    ncv = -1.0f;
                unsigned ncp = 0xffffffffu;
                #pragma unroll
                for (int s = 0; s < 16; s++) {
                    int a = (s << 9) + tid;
                    float dx = __fsub_rn(spx[a], lx);
                    float dy = __fsub_rn(spy[a], ly);
                    float dz = __fsub_rn(spz[a], lz);
                    float d  = __fmaf_rn(dz, dz, __fmaf_rn(dx, dx, __fmul_rn(dy, dy)));
                    float nd = fminf(dd[s], d);
                    dd[s] = nd;
                    unsigned pk = opack[s];
                    if (nd > ncv || (nd == ncv && pk < ncp)) { ncv = nd; ncp = pk; }
                }
                cvA = ncv; cpA = ncp;
            }
        }
        // ---- chunk B ----
        {
            float ax = fmaxf(fmaxf(Bxn - lx, lx - Bxm), 0.f);
            float ay = fmaxf(fmaxf(Byn - ly, ly - Bym), 0.f);
            float az = fmaxf(fmaxf(Bzn - lz, lz - Bzm), 0.f);
            float lb = ax * ax + ay * ay + az * az;
            if (!(lb * 0.9999f >= cvB)) {
                float    ncv = -1.0f;
                unsigned ncp = 0xffffffffu;
                #pragma unroll
                for (int s = 16; s < 32; s++) {
                    int a = (s << 9) + tid;
                    float dx = __fsub_rn(spx[a], lx);
                    float dy = __fsub_rn(spy[a], ly);
                    float dz = __fsub_rn(spz[a], lz);
                    float d  = __fmaf_rn(dz, dz, __fmaf_rn(dx, dx, __fmul_rn(dy, dy)));
                    float nd = fminf(dd[s], d);
                    dd[s] = nd;
                    unsigned pk = opack[s];
                    if (nd > ncv || (nd == ncv && pk < ncp)) { ncv = nd; ncp = pk; }
                }
                cvB = ncv; cpB = ncp;
            }
        }
        // ---- thread combine (max value, tie -> min pack) ----
        float    cv;
        unsigned cp;
        if (cvA > cvB || (cvA == cvB && cpA < cpB)) { cv = cvA; cp = cpA; }
        else                                        { cv = cvB; cp = cpB; }

        // ---- warp argmax via redux (d >= 0 so u32 bit order == float order) ----
        unsigned cb = __float_as_uint(cv);
        unsigned wm = __reduce_max_sync(0xffffffffu, cb);
        unsigned cand = (cb == wm) ? cp : 0xffffffffu;
        unsigned wp = __reduce_min_sync(0xffffffffu, cand);
        if (lane == 0) { svb[buf][wid] = wm; spk[buf][wid] = wp; }
        __syncthreads();

        // ---- all warps redundantly reduce the 16 warp results ----
        unsigned v  = svb[buf][lane & 15];
        unsigned pk = spk[buf][lane & 15];
        unsigned gm = __reduce_max_sync(0xffffffffu, v);
        unsigned c2 = (v == gm) ? pk : 0xffffffffu;
        unsigned gp = __reduce_min_sync(0xffffffffu, c2);
        int pos = (int)(gp & 16383u);
        int ad  = ((pos & 31) << 9) | (pos >> 5);
        lx = spx[ad]; ly = spy[ad]; lz = spz[ad];
        if (tid == 0) g_idx[t] = (int)(gp >> 14);
    }
}

// ============================================================
// 2. Gather sampled coordinates + n_o scalars into output
// ============================================================
__global__ void gather_kernel(const float* __restrict__ p, float* __restrict__ out)
{
    int e = blockIdx.x * blockDim.x + threadIdx.x;
    if (e < MTOT * 3) {
        int q = e / 3, d = e - 3 * q;
        float v = p[g_idx[q] * 3 + d];
        int pos = (q < M1) ? (OFF_NP1 + e) : (OFF_NP2 + (e - M1 * 3));
        out[pos] = v;
    } else if (e == MTOT * 3) {
        out[OFF_NO1] = 4096.0f;
    } else if (e == MTOT * 3 + 1) {
        out[OFF_NO2] = 4096.0f;
    }
}

// ============================================================
// 3. KNN — thread-per-query, SMEM point tiles (broadcast reads),
//    per-thread sorted top-16
// ============================================================
__global__ void __launch_bounds__(128, 8)
knn_kernel(const float* __restrict__ p)
{
    __shared__ float4 tile[2048];   // 32 KB
    int tid = threadIdx.x;
    int qid = blockIdx.x * 128 + tid;
    int qi = g_idx[qid];
    float qx = p[3 * qi], qy = p[3 * qi + 1], qz = p[3 * qi + 2];
    float qq = qx * qx + qy * qy + qz * qz;

    float bd[16]; int bn[16];
    #pragma unroll
    for (int i = 0; i < 16; i++) { bd[i] = 3.4e38f; bn[i] = 0; }

    for (int tb = 0; tb < 8; tb++) {
        for (int i = tid; i < 2048; i += 128) {
            int g = tb * 2048 + i;
            float x = p[3 * g], y = p[3 * g + 1], z = p[3 * g + 2];
            tile[i] = make_float4(x, y, z, x * x + y * y + z * z);
        }
        __syncthreads();
        for (int j = 0; j < 2048; j++) {
            float4 t = tile[j];
            float dot = fmaf(qx, t.x, fmaf(qy, t.y, qz * t.z));
            float d = fmaf(-2.0f, dot, qq) + t.w;
            if (d < bd[15]) {
                int g = tb * 2048 + j;
                int k = 15;
                while (k > 0 && bd[k - 1] > d) {
                    bd[k] = bd[k - 1]; bn[k] = bn[k - 1]; --k;
                }
                bd[k] = d; bn[k] = g;
            }
        }
        __syncthreads();
    }
    #pragma unroll
    for (int i = 0; i < 16; i++) g_knn[qid * 16 + i] = bn[i];
}

// ============================================================
// 4. Grouped feature build + linear (67 -> 128), h to global
// ============================================================
__global__ void __launch_bounds__(128, 8)
mlp_kernel(const float* __restrict__ p, const float* __restrict__ x,
           const float* __restrict__ W)
{
    __shared__ float f[16 * 68];
    __shared__ int   sn[16];
    __shared__ float qc[3];
    int tid = threadIdx.x, q = blockIdx.x;
    if (tid < 16) sn[tid] = g_knn[q * 16 + tid];
    if (tid < 3)  qc[tid] = p[g_idx[q] * 3 + tid];
    __syncthreads();
    for (int e = tid; e < 16 * CF; e += 128) {
        int s = e / CF, k = e - CF * s;
        int n = sn[s];
        float v = (k < 3) ? (p[n * 3 + k] - qc[k]) : x[n * 64 + (k - 3)];
        f[s * 68 + k] = v;
    }
    __syncthreads();
    float acc[16];
    #pragma unroll
    for (int s = 0; s < 16; s++) acc[s] = 0.f;
    int c = tid;
    for (int k = 0; k < CF; k++) {
        float wv = W[k * 128 + c];
        #pragma unroll
        for (int s = 0; s < 16; s++)
            acc[s] = fmaf(f[s * 68 + k], wv, acc[s]);
    }
    #pragma unroll
    for (int s = 0; s < 16; s++)
        g_h[((size_t)q * 16 + s) * 128 + c] = acc[s];
}

// ============================================================
// 5a. BN partial sums — coalesced float4 reads, fixed-order reduce
//     128 blocks (64 per half), 256 threads, each block covers
//     131072 contiguous floats (1024 rows).
// ============================================================
__global__ void __launch_bounds__(256, 4)
stats_part_kernel()
{
    __shared__ float sb1[1024], sb2[1024];
    int tid = threadIdx.x;
    const float* base = g_h + (size_t)blockIdx.x * 131072;

    float s1[4] = {0.f, 0.f, 0.f, 0.f};
    float s2[4] = {0.f, 0.f, 0.f, 0.f};
    #pragma unroll 4
    for (int it = 0; it < 128; it++) {
        const float4 v4 = *reinterpret_cast<const float4*>(base + it * 1024 + tid * 4);
        s1[0] += v4.x; s2[0] = fmaf(v4.x, v4.x, s2[0]);
        s1[1] += v4.y; s2[1] = fmaf(v4.y, v4.y, s2[1]);
        s1[2] += v4.z; s2[2] = fmaf(v4.z, v4.z, s2[2]);
        s1[3] += v4.w; s2[3] = fmaf(v4.w, v4.w, s2[3]);
    }
    #pragma unroll
    for (int k = 0; k < 4; k++) { sb1[tid * 4 + k] = s1[k]; sb2[tid * 4 + k] = s2[k]; }
    __syncthreads();
    // threads 0..31 own channel groups: channels of thread t are (4t)&127
    if (tid < 32) {
        #pragma unroll
        for (int k = 0; k < 4; k++) {
            float a1 = 0.f, a2 = 0.f;
            #pragma unroll
            for (int j = 0; j < 8; j++) {
                a1 += sb1[(tid + 32 * j) * 4 + k];
                a2 += sb2[(tid + 32 * j) * 4 + k];
            }
            int c = (tid * 4 + k) & 127;
            g_part1[blockIdx.x * 128 + c] = a1;
            g_part2[blockIdx.x * 128 + c] = a2;
        }
    }
}

// ============================================================
// 5b. BN finalize — 256 threads = (half, channel) pairs
// ============================================================
__global__ void stats_fin_kernel(const float* __restrict__ gamma,
                                 const float* __restrict__ beta)
{
    int tid = threadIdx.x;          // 0..255
    int half = tid >> 7, c = tid & 127;
    float s1 = 0.f, s2 = 0.f;
    for (int j = 0; j < 64; j++) {
        s1 += g_part1[(half * 64 + j) * 128 + c];
        s2 += g_part2[(half * 64 + j) * 128 + c];
    }
    float mean = s1 * (1.f / 65536.f);
    float var  = s2 * (1.f / 65536.f) - mean * mean;
    float sc = rsqrtf(var + 1e-5f) * gamma[c];
    g_scale[tid] = sc;
    g_shift[tid] = beta[c] - mean * sc;
}

// ============================================================
// 6. BN apply + ReLU + max-pool over nsample, write x1/x2
// ============================================================
__global__ void __launch_bounds__(128, 8)
pool_kernel(float* __restrict__ out)
{
    int q = blockIdx.x, c = threadIdx.x;
    int half = (q >= M1);
    float sc = g_scale[half * 128 + c];
    float sh = g_shift[half * 128 + c];
    float m = 0.f;   // relu floor; max over 16 relu outputs >= 0
    const float* hb = g_h + ((size_t)q * 16) * 128 + c;
    #pragma unroll
    for (int s = 0; s < 16; s++) {
        float v = fmaf(hb[s * 128], sc, sh);
        v = fmaxf(v, 0.f);
        m = fmaxf(m, v);
    }
    int pos = (q < M1) ? (OFF_X1 + q * 128 + c)
                       : (OFF_X2 + (q - M1) * 128 + c);
    out[pos] = m;
}

// ============================================================
extern "C" void kernel_launch(void* const* d_in, const int* in_sizes, int n_in,
                              void* d_out, int out_size)
{
    const float* p     = (const float*)d_in[0];
    const float* x     = (const float*)d_in[1];
    // d_in[2] = o (int32, unused: single batch)
    const float* W     = (const float*)d_in[3];
    const float* gamma = (const float*)d_in[4];
    const float* beta  = (const float*)d_in[5];
    float* out = (float*)d_out;

    cudaFuncSetAttribute(sort_kernel,
                         cudaFuncAttributeMaxDynamicSharedMemorySize,
                         NPTS * sizeof(unsigned long long));
    cudaFuncSetAttribute(fps_kernel,
                         cudaFuncAttributeMaxDynamicSharedMemorySize,
                         NPTS * 3 * sizeof(float));

    sort_kernel<<<1, 1024, NPTS * sizeof(unsigned long long)>>>(p);
    fps_kernel<<<1, 512, NPTS * 3 * sizeof(float)>>>(p);
    gather_kernel<<<(MTOT * 3 + 2 + 255) / 256, 256>>>(p, out);
    knn_kernel<<<64, 128>>>(p);
    mlp_kernel<<<MTOT, 128>>>(p, x, W);
    stats_part_kernel<<<128, 256>>>();
    stats_fin_kernel<<<1, 256>>>(gamma, beta);
    pool_kernel<<<MTOT, 128>>>(out);
}

// round 8
// speedup vs baseline: 1.9610x; 1.0465x over previous
#include <cuda_runtime.h>

#define NPTS 16384
#define MTOT 8192
#define M1   4096
#define CIN  64
#define COUT 128
#define KNNK 16
#define CF   67   // 3 + 64

// ---- output layout (floats) ----
#define OFF_NP1 0
#define OFF_X1  12288
#define OFF_NO1 536576
#define OFF_NP2 536577
#define OFF_X2  548865
#define OFF_NO2 1073153

// ---- device scratch (no allocations allowed) ----
__device__ int   g_idx[MTOT];
__device__ int   g_knn[MTOT * KNNK];
__device__ float g_h[(size_t)MTOT * KNNK * COUT];   // 64 MB
__device__ float g_scale[2 * COUT];
__device__ float g_shift[2 * COUT];
// sorted point arrays (Morton order)
__device__ float g_sx[NPTS];
__device__ float g_sy[NPTS];
__device__ float g_sz[NPTS];
__device__ unsigned g_sopack[NPTS];   // (orig_idx << 14) | sorted_pos
// BN partial sums
__device__ float g_part1[128 * 128];
__device__ float g_part2[128 * 128];

// ============================================================
// 0. Morton sort — single CTA bitonic sort of (code<<14 | idx)
// ============================================================
__device__ __forceinline__ unsigned expand10(unsigned v)
{
    v &= 1023u;
    v = (v | (v << 16)) & 0x030000FFu;
    v = (v | (v << 8))  & 0x0300F00Fu;
    v = (v | (v << 4))  & 0x030C30C3u;
    v = (v | (v << 2))  & 0x09249249u;
    return v;
}

__global__ void __launch_bounds__(1024, 1)
sort_kernel(const float* __restrict__ p)
{
    extern __shared__ unsigned long long key[];   // 16384 * 8B = 128KB
    __shared__ float rmin[3][32], rmax[3][32];
    __shared__ float bb[6];

    int tid = threadIdx.x, lane = tid & 31, wid = tid >> 5;

    float mn[3] = {1e30f, 1e30f, 1e30f};
    float mx[3] = {-1e30f, -1e30f, -1e30f};
    for (int i = tid; i < NPTS; i += 1024) {
        float c[3] = {p[3 * i], p[3 * i + 1], p[3 * i + 2]};
        #pragma unroll
        for (int d = 0; d < 3; d++) {
            mn[d] = fminf(mn[d], c[d]);
            mx[d] = fmaxf(mx[d], c[d]);
        }
    }
    #pragma unroll
    for (int off = 16; off > 0; off >>= 1) {
        #pragma unroll
        for (int d = 0; d < 3; d++) {
            mn[d] = fminf(mn[d], __shfl_xor_sync(0xffffffffu, mn[d], off));
            mx[d] = fmaxf(mx[d], __shfl_xor_sync(0xffffffffu, mx[d], off));
        }
    }
    if (lane == 0) {
        #pragma unroll
        for (int d = 0; d < 3; d++) { rmin[d][wid] = mn[d]; rmax[d][wid] = mx[d]; }
    }
    __syncthreads();
    if (tid < 32) {
        #pragma unroll
        for (int d = 0; d < 3; d++) { mn[d] = rmin[d][tid]; mx[d] = rmax[d][tid]; }
        #pragma unroll
        for (int off = 16; off > 0; off >>= 1) {
            #pragma unroll
            for (int d = 0; d < 3; d++) {
                mn[d] = fminf(mn[d], __shfl_xor_sync(0xffffffffu, mn[d], off));
                mx[d] = fmaxf(mx[d], __shfl_xor_sync(0xffffffffu, mx[d], off));
            }
        }
        if (tid == 0) {
            #pragma unroll
            for (int d = 0; d < 3; d++) { bb[d] = mn[d]; bb[3 + d] = mx[d]; }
        }
    }
    __syncthreads();

    float ox = bb[0], oy = bb[1], oz = bb[2];
    float scx = 1023.0f / fmaxf(bb[3] - bb[0], 1e-20f);
    float scy = 1023.0f / fmaxf(bb[4] - bb[1], 1e-20f);
    float scz = 1023.0f / fmaxf(bb[5] - bb[2], 1e-20f);

    for (int i = tid; i < NPTS; i += 1024) {
        unsigned xi = (unsigned)fminf(fmaxf((p[3 * i]     - ox) * scx, 0.f), 1023.f);
        unsigned yi = (unsigned)fminf(fmaxf((p[3 * i + 1] - oy) * scy, 0.f), 1023.f);
        unsigned zi = (unsigned)fminf(fmaxf((p[3 * i + 2] - oz) * scz, 0.f), 1023.f);
        unsigned code = (expand10(xi) << 2) | (expand10(yi) << 1) | expand10(zi);
        key[i] = ((unsigned long long)code << 14) | (unsigned)i;
    }
    __syncthreads();

    // bitonic sort
    for (int k = 2; k <= NPTS; k <<= 1) {
        for (int j = k >> 1; j > 0; j >>= 1) {
            for (int t = tid; t < NPTS; t += 1024) {
                int ixj = t ^ j;
                if (ixj > t) {
                    bool up = ((t & k) == 0);
                    unsigned long long a = key[t], b = key[ixj];
                    if ((a > b) == up) { key[t] = b; key[ixj] = a; }
                }
            }
            __syncthreads();
        }
    }

    for (int i = tid; i < NPTS; i += 1024) {
        int oi = (int)(key[i] & 16383ull);
        g_sx[i] = p[3 * oi];
        g_sy[i] = p[3 * oi + 1];
        g_sz[i] = p[3 * oi + 2];
        g_sopack[i] = ((unsigned)oi << 14) | (unsigned)i;
    }
}

// ============================================================
// 1. FPS — single CTA, 512 threads, ONE 32-point Morton chunk
//    per thread (chunk id == thread id), transposed SMEM
//    (conflict-free), one skip branch + one barrier per iter.
//    Distance = fma(dz,dz, fma(dx,dx, dy*dy))  [validated R5]
//    Tie-break: min (orig_idx<<14|pos)  == first original index.
// ============================================================
__global__ void __launch_bounds__(512, 1)
fps_kernel(const float* __restrict__ p)
{
    extern __shared__ float sm[];
    float2* sxy = reinterpret_cast<float2*>(sm);   // [32 slots][512 chunks], 128KB
    float*  szz = sm + 2 * NPTS;                   // 64KB
    __shared__ unsigned svb[2][16], spk[2][16];

    int tid = threadIdx.x, lane = tid & 31, wid = tid >> 5;

    for (int i = tid; i < NPTS; i += 512) {
        int a = ((i & 31) << 9) | (i >> 5);
        sxy[a] = make_float2(g_sx[i], g_sy[i]);
        szz[a] = g_sz[i];
    }
    unsigned opack[32];
    #pragma unroll
    for (int s = 0; s < 32; s++)
        opack[s] = g_sopack[(tid << 5) + s];

    if (tid == 0) g_idx[0] = 0;
    __syncthreads();

    // chunk bbox over own 32 points (slot-major, lane-contiguous)
    float bxn = 1e30f, byn = 1e30f, bzn = 1e30f;
    float bxm = -1e30f, bym = -1e30f, bzm = -1e30f;
    #pragma unroll
    for (int s = 0; s < 32; s++) {
        float2 xy = sxy[(s << 9) + tid];
        float z = szz[(s << 9) + tid];
        bxn = fminf(bxn, xy.x); bxm = fmaxf(bxm, xy.x);
        byn = fminf(byn, xy.y); bym = fmaxf(bym, xy.y);
        bzn = fminf(bzn, z);    bzm = fmaxf(bzm, z);
    }

    float dd[32];
    #pragma unroll
    for (int s = 0; s < 32; s++) dd[s] = 1e10f;
    float    cv = 1e10f;      // cached chunk max (forces compute at t=1)
    unsigned cp = 0xffffffffu;

    float lx = p[0], ly = p[1], lz = p[2];

    for (int t = 1; t < MTOT; ++t) {
        int buf = t & 1;

        // bbox lower bound on squared distance to new point
        float ax = fmaxf(fmaxf(bxn - lx, lx - bxm), 0.f);
        float ay = fmaxf(fmaxf(byn - ly, ly - bym), 0.f);
        float az = fmaxf(fmaxf(bzn - lz, lz - bzm), 0.f);
        float lb = __fmaf_rn(az, az, __fmaf_rn(ay, ay, ax * ax));

        if (!(lb * 0.9999f >= cv)) {
            float    ncv = -1.0f;
            unsigned ncp = 0xffffffffu;
            #pragma unroll
            for (int s = 0; s < 32; s++) {
                int a = (s << 9) + tid;
                float2 xy = sxy[a];
                float dx = __fsub_rn(xy.x, lx);
                float dy = __fsub_rn(xy.y, ly);
                float dz = __fsub_rn(szz[a], lz);
                float d  = __fmaf_rn(dz, dz, __fmaf_rn(dx, dx, __fmul_rn(dy, dy)));
                float nd = fminf(dd[s], d);
                dd[s] = nd;
                unsigned pk = opack[s];
                if (nd > ncv || (nd == ncv && pk < ncp)) { ncv = nd; ncp = pk; }
            }
            cv = ncv; cp = ncp;
        }

        // warp argmax via redux (d >= 0 so u32 bit order == float order)
        unsigned cb = __float_as_uint(cv);
        unsigned wm = __reduce_max_sync(0xffffffffu, cb);
        unsigned cand = (cb == wm) ? cp : 0xffffffffu;
        unsigned wp = __reduce_min_sync(0xffffffffu, cand);
        if (lane == 0) { svb[buf][wid] = wm; spk[buf][wid] = wp; }
        __syncthreads();

        // all warps redundantly reduce the 16 warp results
        unsigned v  = svb[buf][lane & 15];
        unsigned pk = spk[buf][lane & 15];
        unsigned gm = __reduce_max_sync(0xffffffffu, v);
        unsigned c2 = (v == gm) ? pk : 0xffffffffu;
        unsigned gp = __reduce_min_sync(0xffffffffu, c2);
        int pos = (int)(gp & 16383u);
        int ad  = ((pos & 31) << 9) | (pos >> 5);
        float2 wxy = sxy[ad];
        lx = wxy.x; ly = wxy.y; lz = szz[ad];
        if (tid == 0) g_idx[t] = (int)(gp >> 14);
    }
}

// ============================================================
// 2. Gather sampled coordinates + n_o scalars into output
// ============================================================
__global__ void gather_kernel(const float* __restrict__ p, float* __restrict__ out)
{
    int e = blockIdx.x * blockDim.x + threadIdx.x;
    if (e < MTOT * 3) {
        int q = e / 3, d = e - 3 * q;
        float v = p[g_idx[q] * 3 + d];
        int pos = (q < M1) ? (OFF_NP1 + e) : (OFF_NP2 + (e - M1 * 3));
        out[pos] = v;
    } else if (e == MTOT * 3) {
        out[OFF_NO1] = 4096.0f;
    } else if (e == MTOT * 3 + 1) {
        out[OFF_NO2] = 4096.0f;
    }
}

// ============================================================
// 3. KNN — thread-per-query, SMEM point tiles (broadcast reads),
//    per-thread sorted top-16
// ============================================================
__global__ void __launch_bounds__(128, 8)
knn_kernel(const float* __restrict__ p)
{
    __shared__ float4 tile[2048];   // 32 KB
    int tid = threadIdx.x;
    int qid = blockIdx.x * 128 + tid;
    int qi = g_idx[qid];
    float qx = p[3 * qi], qy = p[3 * qi + 1], qz = p[3 * qi + 2];
    float qq = qx * qx + qy * qy + qz * qz;

    float bd[16]; int bn[16];
    #pragma unroll
    for (int i = 0; i < 16; i++) { bd[i] = 3.4e38f; bn[i] = 0; }

    for (int tb = 0; tb < 8; tb++) {
        for (int i = tid; i < 2048; i += 128) {
            int g = tb * 2048 + i;
            float x = p[3 * g], y = p[3 * g + 1], z = p[3 * g + 2];
            tile[i] = make_float4(x, y, z, x * x + y * y + z * z);
        }
        __syncthreads();
        for (int j = 0; j < 2048; j++) {
            float4 t = tile[j];
            float dot = fmaf(qx, t.x, fmaf(qy, t.y, qz * t.z));
            float d = fmaf(-2.0f, dot, qq) + t.w;
            if (d < bd[15]) {
                int g = tb * 2048 + j;
                int k = 15;
                while (k > 0 && bd[k - 1] > d) {
                    bd[k] = bd[k - 1]; bn[k] = bn[k - 1]; --k;
                }
                bd[k] = d; bn[k] = g;
            }
        }
        __syncthreads();
    }
    #pragma unroll
    for (int i = 0; i < 16; i++) g_knn[qid * 16 + i] = bn[i];
}

// ============================================================
// 4. Grouped feature build + linear (67 -> 128), h to global
// ============================================================
__global__ void __launch_bounds__(128, 8)
mlp_kernel(const float* __restrict__ p, const float* __restrict__ x,
           const float* __restrict__ W)
{
    __shared__ float f[16 * 68];
    __shared__ int   sn[16];
    __shared__ float qc[3];
    int tid = threadIdx.x, q = blockIdx.x;
    if (tid < 16) sn[tid] = g_knn[q * 16 + tid];
    if (tid < 3)  qc[tid] = p[g_idx[q] * 3 + tid];
    __syncthreads();
    for (int e = tid; e < 16 * CF; e += 128) {
        int s = e / CF, k = e - CF * s;
        int n = sn[s];
        float v = (k < 3) ? (p[n * 3 + k] - qc[k]) : x[n * 64 + (k - 3)];
        f[s * 68 + k] = v;
    }
    __syncthreads();
    float acc[16];
    #pragma unroll
    for (int s = 0; s < 16; s++) acc[s] = 0.f;
    int c = tid;
    for (int k = 0; k < CF; k++) {
        float wv = W[k * 128 + c];
        #pragma unroll
        for (int s = 0; s < 16; s++)
            acc[s] = fmaf(f[s * 68 + k], wv, acc[s]);
    }
    #pragma unroll
    for (int s = 0; s < 16; s++)
        g_h[((size_t)q * 16 + s) * 128 + c] = acc[s];
}

// ============================================================
// 5a. BN partial sums — coalesced float4 reads, fixed-order reduce
// ============================================================
__global__ void __launch_bounds__(256, 4)
stats_part_kernel()
{
    __shared__ float sb1[1024], sb2[1024];
    int tid = threadIdx.x;
    const float* base = g_h + (size_t)blockIdx.x * 131072;

    float s1[4] = {0.f, 0.f, 0.f, 0.f};
    float s2[4] = {0.f, 0.f, 0.f, 0.f};
    #pragma unroll 4
    for (int it = 0; it < 128; it++) {
        const float4 v4 = *reinterpret_cast<const float4*>(base + it * 1024 + tid * 4);
        s1[0] += v4.x; s2[0] = fmaf(v4.x, v4.x, s2[0]);
        s1[1] += v4.y; s2[1] = fmaf(v4.y, v4.y, s2[1]);
        s1[2] += v4.z; s2[2] = fmaf(v4.z, v4.z, s2[2]);
        s1[3] += v4.w; s2[3] = fmaf(v4.w, v4.w, s2[3]);
    }
    #pragma unroll
    for (int k = 0; k < 4; k++) { sb1[tid * 4 + k] = s1[k]; sb2[tid * 4 + k] = s2[k]; }
    __syncthreads();
    if (tid < 32) {
        #pragma unroll
        for (int k = 0; k < 4; k++) {
            float a1 = 0.f, a2 = 0.f;
            #pragma unroll
            for (int j = 0; j < 8; j++) {
                a1 += sb1[(tid + 32 * j) * 4 + k];
                a2 += sb2[(tid + 32 * j) * 4 + k];
            }
            int c = (tid * 4 + k) & 127;
            g_part1[blockIdx.x * 128 + c] = a1;
            g_part2[blockIdx.x * 128 + c] = a2;
        }
    }
}

// ============================================================
// 5b. BN finalize — 256 threads = (half, channel) pairs
// ============================================================
__global__ void stats_fin_kernel(const float* __restrict__ gamma,
                                 const float* __restrict__ beta)
{
    int tid = threadIdx.x;          // 0..255
    int half = tid >> 7, c = tid & 127;
    float s1 = 0.f, s2 = 0.f;
    for (int j = 0; j < 64; j++) {
        s1 += g_part1[(half * 64 + j) * 128 + c];
        s2 += g_part2[(half * 64 + j) * 128 + c];
    }
    float mean = s1 * (1.f / 65536.f);
    float var  = s2 * (1.f / 65536.f) - mean * mean;
    float sc = rsqrtf(var + 1e-5f) * gamma[c];
    g_scale[tid] = sc;
    g_shift[tid] = beta[c] - mean * sc;
}

// ============================================================
// 6. BN apply + ReLU + max-pool over nsample, write x1/x2
// ============================================================
__global__ void __launch_bounds__(128, 8)
pool_kernel(float* __restrict__ out)
{
    int q = blockIdx.x, c = threadIdx.x;
    int half = (q >= M1);
    float sc = g_scale[half * 128 + c];
    float sh = g_shift[half * 128 + c];
    float m = 0.f;   // relu floor; max over 16 relu outputs >= 0
    const float* hb = g_h + ((size_t)q * 16) * 128 + c;
    #pragma unroll
    for (int s = 0; s < 16; s++) {
        float v = fmaf(hb[s * 128], sc, sh);
        v = fmaxf(v, 0.f);
        m = fmaxf(m, v);
    }
    int pos = (q < M1) ? (OFF_X1 + q * 128 + c)
                       : (OFF_X2 + (q - M1) * 128 + c);
    out[pos] = m;
}

// ============================================================
extern "C" void kernel_launch(void* const* d_in, const int* in_sizes, int n_in,
                              void* d_out, int out_size)
{
    const float* p     = (const float*)d_in[0];
    const float* x     = (const float*)d_in[1];
    // d_in[2] = o (int32, unused: single batch)
    const float* W     = (const float*)d_in[3];
    const float* gamma = (const float*)d_in[4];
    const float* beta  = (const float*)d_in[5];
    float* out = (float*)d_out;

    cudaFuncSetAttribute(sort_kernel,
                         cudaFuncAttributeMaxDynamicSharedMemorySize,
                         NPTS * sizeof(unsigned long long));
    cudaFuncSetAttribute(fps_kernel,
                         cudaFuncAttributeMaxDynamicSharedMemorySize,
                         NPTS * 3 * sizeof(float));

    sort_kernel<<<1, 1024, NPTS * sizeof(unsigned long long)>>>(p);
    fps_kernel<<<1, 512, NPTS * 3 * sizeof(float)>>>(p);
    gather_kernel<<<(MTOT * 3 + 2 + 255) / 256, 256>>>(p, out);
    knn_kernel<<<64, 128>>>(p);
    mlp_kernel<<<MTOT, 128>>>(p, x, W);
    stats_part_kernel<<<128, 256>>>();
    stats_fin_kernel<<<1, 256>>>(gamma, beta);
    pool_kernel<<<MTOT, 128>>>(out);
}